// round 5
// baseline (speedup 1.0000x reference)
#include <cuda_runtime.h>
#include <math.h>

#define Bsz 64
#define Tsz 2000
#define Esz 512
#define Rsz 1024
#define Asz 512
#define Msz 8
#define KS 16
#define TSPLIT 40
#define TCHUNK (Tsz / TSPLIT)   // 50

// ---------------- scratch -----------------------------------------------------
__device__ float g_part1[KS * Bsz * Asz];       // stage-1 split-K partials
__device__ float g_part2[KS * Bsz * Asz];       // stage-2 split-K partials
__device__ float g_cpart[TSPLIT * Bsz * Esz];   // context partials
__device__ float g_esum[TSPLIT * Bsz];          // exp-sum partials
__device__ float g_wmix[Bsz * Msz];
__device__ float g_loc[Bsz * Msz];
__device__ float g_scale[Bsz * Msz];
__device__ int   g_ctr[Bsz];                    // zero-init; reset by last block

// ---------------- stage 1: part1[ks] = tanh(ash) @ W1^T (split-K 16) ----------
__global__ void gemm1_kernel(const float* __restrict__ Ain,
                             const float* __restrict__ W) {
    __shared__ float As[64][33];
    __shared__ float Ws[64][33];
    const int nbase = blockIdx.x * 64;
    const int k0 = blockIdx.y * (Rsz / KS);
    const int tx = threadIdx.x & 15, ty = threadIdx.x >> 4;
    const int lane = threadIdx.x & 31, wrp = threadIdx.x >> 5;

    float acc[4][4] = {};
    for (int kk = 0; kk < Rsz / KS; kk += 32) {
        const int kc = k0 + kk + lane;
#pragma unroll
        for (int r = wrp; r < 64; r += 8) {
            As[r][lane] = tanhf(Ain[r * Rsz + kc]);
            Ws[r][lane] = W[(nbase + r) * Rsz + kc];
        }
        __syncthreads();
#pragma unroll
        for (int k = 0; k < 32; k++) {
            float a[4], w[4];
#pragma unroll
            for (int i = 0; i < 4; i++) a[i] = As[ty * 4 + i][k];
#pragma unroll
            for (int j = 0; j < 4; j++) w[j] = Ws[tx * 4 + j][k];
#pragma unroll
            for (int i = 0; i < 4; i++)
#pragma unroll
                for (int j = 0; j < 4; j++) acc[i][j] = fmaf(a[i], w[j], acc[i][j]);
        }
        __syncthreads();
    }
#pragma unroll
    for (int i = 0; i < 4; i++)
#pragma unroll
        for (int j = 0; j < 4; j++)
            g_part1[(blockIdx.y * 64 + ty * 4 + i) * Asz + nbase + tx * 4 + j] = acc[i][j];
}

// ---------------- stage 2: part2[ks] = (sum part1 + b1) @ W2^T (split-K 16) ---
__global__ void gemm2_kernel(const float* __restrict__ W,
                             const float* __restrict__ b1) {
    __shared__ float As[64][33];
    __shared__ float Ws[64][33];
    const int nbase = blockIdx.x * 64;
    const int k0 = blockIdx.y * (Asz / KS);
    const int tx = threadIdx.x & 15, ty = threadIdx.x >> 4;
    const int lane = threadIdx.x & 31, wrp = threadIdx.x >> 5;

    float acc[4][4] = {};
    for (int kk = 0; kk < Asz / KS; kk += 32) {
        const int kc = k0 + kk + lane;
        const float bb = b1[kc];
#pragma unroll
        for (int r = wrp; r < 64; r += 8) {
            float s = bb;
#pragma unroll
            for (int p = 0; p < KS; p++) s += g_part1[(p * 64 + r) * Asz + kc];
            As[r][lane] = s;
            Ws[r][lane] = W[(nbase + r) * Asz + kc];
        }
        __syncthreads();
#pragma unroll
        for (int k = 0; k < 32; k++) {
            float a[4], w[4];
#pragma unroll
            for (int i = 0; i < 4; i++) a[i] = As[ty * 4 + i][k];
#pragma unroll
            for (int j = 0; j < 4; j++) w[j] = Ws[tx * 4 + j][k];
#pragma unroll
            for (int i = 0; i < 4; i++)
#pragma unroll
                for (int j = 0; j < 4; j++) acc[i][j] = fmaf(a[i], w[j], acc[i][j]);
        }
        __syncthreads();
    }
#pragma unroll
    for (int i = 0; i < 4; i++)
#pragma unroll
        for (int j = 0; j < 4; j++)
            g_part2[(blockIdx.y * 64 + ty * 4 + i) * Asz + nbase + tx * 4 + j] = acc[i][j];
}

// ---------------- head: x = tanh(sum part2); y = x@Wlin^T + blin --------------
__global__ void head_kernel(const float* __restrict__ Wlin,
                            const float* __restrict__ blin,
                            const float* __restrict__ prev,
                            float* __restrict__ out_loc) {
    const int b = blockIdx.x;
    const int tid = threadIdx.x;
    const int w = tid >> 5, lane = tid & 31;
    __shared__ float sx[Asz];
    __shared__ float ys[24];

    for (int i = tid; i < Asz; i += 768) {
        float s = 0.0f;
#pragma unroll
        for (int p = 0; p < KS; p++) s += g_part2[(p * 64 + b) * Asz + i];
        sx[i] = tanhf(s);
    }
    __syncthreads();

    if (w < 24) {
        float s = 0.0f;
        const float* wr = Wlin + w * Asz;
        for (int k = lane; k < Asz; k += 32) s = fmaf(sx[k], wr[k], s);
#pragma unroll
        for (int off = 16; off > 0; off >>= 1)
            s += __shfl_down_sync(0xffffffffu, s, off);
        if (lane == 0) ys[w] = s + blin[w];
    }
    __syncthreads();

    if (tid < Msz) {
        const int m = tid;
        float wmix = 1.0f / (1.0f + expf(-ys[m]));
        float loc = prev[b * Msz + m] + 1.0f / (1.0f + expf(-ys[Msz + m]));
        float scl = 1.0f / (1.0f + expf(-ys[2 * Msz + m])) * 2.0f + 1.0f;
        g_wmix[b * Msz + m] = wmix;
        g_loc[b * Msz + m] = loc;
        g_scale[b * Msz + m] = scl;
        out_loc[b * Msz + m] = loc;
    }
}

// ---------------- fused alignment + exp + context + softmax-normalize ----------
// grid (TSPLIT, Bsz), block 128. No max-subtraction needed: alignment in [0,8].
__global__ void __launch_bounds__(128)
ctx_fused_kernel(const float* __restrict__ mem,
                 const unsigned char* __restrict__ mask,
                 float* __restrict__ out_w,
                 float* __restrict__ out_ctx) {
    const int s = blockIdx.x;
    const int b = blockIdx.y;
    const int tid = threadIdx.x;
    const int lane = tid & 31, wrp = tid >> 5;
    const int t0 = s * TCHUNK;

    __shared__ float ex[TCHUNK];
    __shared__ float sw[Msz], sl[Msz], ss[Msz];
    __shared__ float red[4];

    if (tid < Msz) {
        sw[tid] = g_wmix[b * Msz + tid];
        sl[tid] = g_loc[b * Msz + tid];
        ss[tid] = g_scale[b * Msz + tid];
    }
    __syncthreads();

    // alignment + exp for this block's t-chunk (unnormalized weights)
    if (tid < TCHUNK) {
        const int t = t0 + tid;
        float al = 0.0f;
        const float ft = (float)t;
#pragma unroll
        for (int m = 0; m < Msz; m++) {
            float d = sl[m] - ft;
            float sc = ss[m];
            float z = 0.5f * (erff((d + 0.5f) * sc) - erff((d - 0.5f) * sc));
            al = fmaf(z, sw[m], al);
        }
        if (mask[b * Tsz + t]) al = 0.0f;
        float e = __expf(al);
        ex[tid] = e;
        out_w[b * Tsz + t] = e;             // rescaled by the last block
    }
    __syncthreads();

    // block partial exp-sum
    {
        float v = (tid < TCHUNK) ? ex[tid] : 0.0f;
#pragma unroll
        for (int off = 16; off > 0; off >>= 1)
            v += __shfl_xor_sync(0xffffffffu, v, off);
        if (lane == 0) red[wrp] = v;
        __syncthreads();
        if (tid == 0) g_esum[s * Bsz + b] = red[0] + red[1] + red[2] + red[3];
    }

    // HBM-bound stream. Two independent accumulators + full unroll so ptxas
    // front-batches the LDG.128s (raise in-flight loads per warp).
    const float4* mrow = (const float4*)(mem + (size_t)b * Tsz * Esz) + t0 * (Esz / 4) + tid;
    float4 acc0 = make_float4(0.f, 0.f, 0.f, 0.f);
    float4 acc1 = make_float4(0.f, 0.f, 0.f, 0.f);
#pragma unroll
    for (int i = 0; i < TCHUNK; i += 2) {
        float w0 = ex[i];
        float w1 = ex[i + 1];
        float4 v0 = __ldcs(mrow + i * (Esz / 4));
        float4 v1 = __ldcs(mrow + (i + 1) * (Esz / 4));
        acc0.x = fmaf(w0, v0.x, acc0.x);
        acc0.y = fmaf(w0, v0.y, acc0.y);
        acc0.z = fmaf(w0, v0.z, acc0.z);
        acc0.w = fmaf(w0, v0.w, acc0.w);
        acc1.x = fmaf(w1, v1.x, acc1.x);
        acc1.y = fmaf(w1, v1.y, acc1.y);
        acc1.z = fmaf(w1, v1.z, acc1.z);
        acc1.w = fmaf(w1, v1.w, acc1.w);
    }
    float4 acc = make_float4(acc0.x + acc1.x, acc0.y + acc1.y,
                             acc0.z + acc1.z, acc0.w + acc1.w);
    ((float4*)g_cpart)[(s * Bsz + b) * (Esz / 4) + tid] = acc;

    // release: partial + esum + out_w globally visible from ALL warps, then signal
    __threadfence();
    __syncthreads();
    __shared__ int done;
    if (tid == 0) done = atomicAdd(&g_ctr[b], 1);
    __syncthreads();

    if (done == TSPLIT - 1) {
        __threadfence();  // acquire
        float S = 0.0f;
#pragma unroll
        for (int p = 0; p < TSPLIT; p++) S += g_esum[p * Bsz + b];
        const float inv = 1.0f / S;

        float4 sum = make_float4(0.f, 0.f, 0.f, 0.f);
#pragma unroll
        for (int p = 0; p < TSPLIT; p++) {
            float4 v = ((const float4*)g_cpart)[(p * Bsz + b) * (Esz / 4) + tid];
            sum.x += v.x; sum.y += v.y; sum.z += v.z; sum.w += v.w;
        }
        sum.x *= inv; sum.y *= inv; sum.z *= inv; sum.w *= inv;
        ((float4*)out_ctx)[b * (Esz / 4) + tid] = sum;

        for (int t = tid; t < Tsz; t += 128)
            out_w[b * Tsz + t] *= inv;

        if (tid == 0) g_ctr[b] = 0;  // reset for next replay
    }
}

// ---------------- launch --------------------------------------------------------
extern "C" void kernel_launch(void* const* d_in, const int* in_sizes, int n_in,
                              void* d_out, int out_size) {
    const float* ash  = (const float*)d_in[0];
    const float* mem  = (const float*)d_in[1];
    const float* prev = (const float*)d_in[2];
    const unsigned char* mask = (const unsigned char*)d_in[3];
    const float* W1   = (const float*)d_in[4];
    const float* b1   = (const float*)d_in[5];
    const float* W2   = (const float*)d_in[6];
    const float* Wlin = (const float*)d_in[7];
    const float* blin = (const float*)d_in[8];

    float* out     = (float*)d_out;
    float* out_ctx = out;
    float* out_w   = out + Bsz * Esz;
    float* out_loc = out_w + Bsz * Tsz;

    gemm1_kernel<<<dim3(Asz / 64, KS), 256>>>(ash, W1);
    gemm2_kernel<<<dim3(Asz / 64, KS), 256>>>(W2, b1);
    head_kernel<<<Bsz, 768>>>(Wlin, blin, prev, out_loc);
    ctx_fused_kernel<<<dim3(TSPLIT, Bsz), 128>>>(mem, mask, out_w, out_ctx);
}

// round 6
// speedup vs baseline: 1.0453x; 1.0453x over previous
#include <cuda_runtime.h>
#include <math.h>

#define Bsz 64
#define Tsz 2000
#define Esz 512
#define Rsz 1024
#define Asz 512
#define Msz 8
#define KS 16
#define TSPLIT 20
#define TCHUNK (Tsz / TSPLIT)    // 100
#define HCHUNK (TCHUNK / 2)      // 50
#define NPART (TSPLIT * 2)       // 40 partial slots per batch

// ---------------- scratch -----------------------------------------------------
__device__ float g_part1[KS * Bsz * Asz];
__device__ float g_part2[KS * Bsz * Asz];
__device__ float g_cpart[NPART * Bsz * Esz];    // context partials (5 MB)
__device__ float g_esum[TSPLIT * Bsz];
__device__ float g_wmix[Bsz * Msz];
__device__ float g_loc[Bsz * Msz];
__device__ float g_scale[Bsz * Msz];
__device__ int   g_ctr[Bsz];                    // zero-init; reset by last block

// ---------------- stage 1: part1[ks] = tanh(ash) @ W1^T (split-K 16) ----------
__global__ void gemm1_kernel(const float* __restrict__ Ain,
                             const float* __restrict__ W) {
    __shared__ float As[64][33];
    __shared__ float Ws[64][33];
    const int nbase = blockIdx.x * 64;
    const int k0 = blockIdx.y * (Rsz / KS);
    const int tx = threadIdx.x & 15, ty = threadIdx.x >> 4;
    const int lane = threadIdx.x & 31, wrp = threadIdx.x >> 5;

    float acc[4][4] = {};
    for (int kk = 0; kk < Rsz / KS; kk += 32) {
        const int kc = k0 + kk + lane;
#pragma unroll
        for (int r = wrp; r < 64; r += 8) {
            As[r][lane] = tanhf(Ain[r * Rsz + kc]);
            Ws[r][lane] = W[(nbase + r) * Rsz + kc];
        }
        __syncthreads();
#pragma unroll
        for (int k = 0; k < 32; k++) {
            float a[4], w[4];
#pragma unroll
            for (int i = 0; i < 4; i++) a[i] = As[ty * 4 + i][k];
#pragma unroll
            for (int j = 0; j < 4; j++) w[j] = Ws[tx * 4 + j][k];
#pragma unroll
            for (int i = 0; i < 4; i++)
#pragma unroll
                for (int j = 0; j < 4; j++) acc[i][j] = fmaf(a[i], w[j], acc[i][j]);
        }
        __syncthreads();
    }
#pragma unroll
    for (int i = 0; i < 4; i++)
#pragma unroll
        for (int j = 0; j < 4; j++)
            g_part1[(blockIdx.y * 64 + ty * 4 + i) * Asz + nbase + tx * 4 + j] = acc[i][j];
}

// ---------------- stage 2: part2[ks] = (sum part1 + b1) @ W2^T (split-K 16) ---
__global__ void gemm2_kernel(const float* __restrict__ W,
                             const float* __restrict__ b1) {
    __shared__ float As[64][33];
    __shared__ float Ws[64][33];
    const int nbase = blockIdx.x * 64;
    const int k0 = blockIdx.y * (Asz / KS);
    const int tx = threadIdx.x & 15, ty = threadIdx.x >> 4;
    const int lane = threadIdx.x & 31, wrp = threadIdx.x >> 5;

    float acc[4][4] = {};
    for (int kk = 0; kk < Asz / KS; kk += 32) {
        const int kc = k0 + kk + lane;
        const float bb = b1[kc];
#pragma unroll
        for (int r = wrp; r < 64; r += 8) {
            float s = bb;
#pragma unroll
            for (int p = 0; p < KS; p++) s += g_part1[(p * 64 + r) * Asz + kc];
            As[r][lane] = s;
            Ws[r][lane] = W[(nbase + r) * Asz + kc];
        }
        __syncthreads();
#pragma unroll
        for (int k = 0; k < 32; k++) {
            float a[4], w[4];
#pragma unroll
            for (int i = 0; i < 4; i++) a[i] = As[ty * 4 + i][k];
#pragma unroll
            for (int j = 0; j < 4; j++) w[j] = Ws[tx * 4 + j][k];
#pragma unroll
            for (int i = 0; i < 4; i++)
#pragma unroll
                for (int j = 0; j < 4; j++) acc[i][j] = fmaf(a[i], w[j], acc[i][j]);
        }
        __syncthreads();
    }
#pragma unroll
    for (int i = 0; i < 4; i++)
#pragma unroll
        for (int j = 0; j < 4; j++)
            g_part2[(blockIdx.y * 64 + ty * 4 + i) * Asz + nbase + tx * 4 + j] = acc[i][j];
}

// ---------------- head: x = tanh(sum part2); y = x@Wlin^T + blin --------------
__global__ void head_kernel(const float* __restrict__ Wlin,
                            const float* __restrict__ blin,
                            const float* __restrict__ prev,
                            float* __restrict__ out_loc) {
    const int b = blockIdx.x;
    const int tid = threadIdx.x;
    const int w = tid >> 5, lane = tid & 31;
    __shared__ float sx[Asz];
    __shared__ float ys[24];

    for (int i = tid; i < Asz; i += 768) {
        float s = 0.0f;
#pragma unroll
        for (int p = 0; p < KS; p++) s += g_part2[(p * 64 + b) * Asz + i];
        sx[i] = tanhf(s);
    }
    __syncthreads();

    if (w < 24) {
        float s = 0.0f;
        const float* wr = Wlin + w * Asz;
        for (int k = lane; k < Asz; k += 32) s = fmaf(sx[k], wr[k], s);
#pragma unroll
        for (int off = 16; off > 0; off >>= 1)
            s += __shfl_down_sync(0xffffffffu, s, off);
        if (lane == 0) ys[w] = s + blin[w];
    }
    __syncthreads();

    if (tid < Msz) {
        const int m = tid;
        float wmix = 1.0f / (1.0f + expf(-ys[m]));
        float loc = prev[b * Msz + m] + 1.0f / (1.0f + expf(-ys[Msz + m]));
        float scl = 1.0f / (1.0f + expf(-ys[2 * Msz + m])) * 2.0f + 1.0f;
        g_wmix[b * Msz + m] = wmix;
        g_loc[b * Msz + m] = loc;
        g_scale[b * Msz + m] = scl;
        out_loc[b * Msz + m] = loc;
    }
}

// ---------------- fused alignment + exp + context + softmax-normalize ----------
// grid (TSPLIT, Bsz), block 256 (8 warps). Warps 0-3 stream rows [t0,t0+50),
// warps 4-7 stream rows [t0+50,t0+100); each half writes its own partial slot.
// No max-subtraction: alignment in [0,8], exp safe, softmax identical.
__global__ void __launch_bounds__(256)
ctx_fused_kernel(const float* __restrict__ mem,
                 const unsigned char* __restrict__ mask,
                 float* __restrict__ out_w,
                 float* __restrict__ out_ctx) {
    const int s = blockIdx.x;
    const int b = blockIdx.y;
    const int tid = threadIdx.x;
    const int lane = tid & 31, wrp = tid >> 5;
    const int t0 = s * TCHUNK;

    __shared__ float ex[TCHUNK];
    __shared__ float sw[Msz], sl[Msz], ss[Msz];
    __shared__ float red[8];

    if (tid < Msz) {
        sw[tid] = g_wmix[b * Msz + tid];
        sl[tid] = g_loc[b * Msz + tid];
        ss[tid] = g_scale[b * Msz + tid];
    }
    __syncthreads();

    // alignment + exp for this block's 100-t chunk (unnormalized weights)
    if (tid < TCHUNK) {
        const int t = t0 + tid;
        float al = 0.0f;
        const float ft = (float)t;
#pragma unroll
        for (int m = 0; m < Msz; m++) {
            float d = sl[m] - ft;
            float sc = ss[m];
            float z = 0.5f * (erff((d + 0.5f) * sc) - erff((d - 0.5f) * sc));
            al = fmaf(z, sw[m], al);
        }
        if (mask[b * Tsz + t]) al = 0.0f;
        float e = __expf(al);
        ex[tid] = e;
        out_w[b * Tsz + t] = e;             // rescaled by the last block
    }
    __syncthreads();

    // block partial exp-sum
    {
        float v = (tid < TCHUNK) ? ex[tid] : 0.0f;
#pragma unroll
        for (int off = 16; off > 0; off >>= 1)
            v += __shfl_xor_sync(0xffffffffu, v, off);
        if (lane == 0) red[wrp] = v;
        __syncthreads();
        if (tid == 0) {
            float S = 0.0f;
#pragma unroll
            for (int w = 0; w < 8; w++) S += red[w];
            g_esum[s * Bsz + b] = S;
        }
    }

    // HBM-bound stream: half-block per 50-row half, R4-proven loop shape.
    const int half = tid >> 7;          // 0 or 1
    const int e4 = tid & 127;
    const float4* mrow = (const float4*)(mem + (size_t)b * Tsz * Esz)
                         + (size_t)(t0 + half * HCHUNK) * (Esz / 4) + e4;
    const float* exh = ex + half * HCHUNK;

    float4 acc = make_float4(0.f, 0.f, 0.f, 0.f);
#pragma unroll 4
    for (int i = 0; i < HCHUNK; i++) {
        float w = exh[i];
        float4 v = __ldcs(mrow + i * (Esz / 4));
        acc.x = fmaf(w, v.x, acc.x);
        acc.y = fmaf(w, v.y, acc.y);
        acc.z = fmaf(w, v.z, acc.z);
        acc.w = fmaf(w, v.w, acc.w);
    }
    ((float4*)g_cpart)[((s * 2 + half) * Bsz + b) * (Esz / 4) + e4] = acc;

    // release: all warps' partials + esum + out_w visible, then signal
    __threadfence();
    __syncthreads();
    __shared__ int done;
    if (tid == 0) done = atomicAdd(&g_ctr[b], 1);
    __syncthreads();

    if (done == TSPLIT - 1) {
        __threadfence();  // acquire
        float S = 0.0f;
#pragma unroll
        for (int p = 0; p < TSPLIT; p++) S += g_esum[p * Bsz + b];
        const float inv = 1.0f / S;

        if (tid < 128) {
            float4 sum = make_float4(0.f, 0.f, 0.f, 0.f);
#pragma unroll
            for (int p = 0; p < NPART; p++) {
                float4 v = ((const float4*)g_cpart)[(p * Bsz + b) * (Esz / 4) + tid];
                sum.x += v.x; sum.y += v.y; sum.z += v.z; sum.w += v.w;
            }
            sum.x *= inv; sum.y *= inv; sum.z *= inv; sum.w *= inv;
            ((float4*)out_ctx)[b * (Esz / 4) + tid] = sum;
        }

        for (int t = tid; t < Tsz; t += 256)
            out_w[b * Tsz + t] *= inv;

        if (tid == 0) g_ctr[b] = 0;  // reset for next replay
    }
}

// ---------------- launch --------------------------------------------------------
extern "C" void kernel_launch(void* const* d_in, const int* in_sizes, int n_in,
                              void* d_out, int out_size) {
    const float* ash  = (const float*)d_in[0];
    const float* mem  = (const float*)d_in[1];
    const float* prev = (const float*)d_in[2];
    const unsigned char* mask = (const unsigned char*)d_in[3];
    const float* W1   = (const float*)d_in[4];
    const float* b1   = (const float*)d_in[5];
    const float* W2   = (const float*)d_in[6];
    const float* Wlin = (const float*)d_in[7];
    const float* blin = (const float*)d_in[8];

    float* out     = (float*)d_out;
    float* out_ctx = out;
    float* out_w   = out + Bsz * Esz;
    float* out_loc = out_w + Bsz * Tsz;

    gemm1_kernel<<<dim3(Asz / 64, KS), 256>>>(ash, W1);
    gemm2_kernel<<<dim3(Asz / 64, KS), 256>>>(W2, b1);
    head_kernel<<<Bsz, 768>>>(Wlin, blin, prev, out_loc);
    ctx_fused_kernel<<<dim3(TSPLIT, Bsz), 256>>>(mem, mask, out_w, out_ctx);
}

// round 7
// speedup vs baseline: 1.0585x; 1.0126x over previous
#include <cuda_runtime.h>
#include <math.h>

#define Bsz 64
#define Tsz 2000
#define Esz 512
#define Rsz 1024
#define Asz 512
#define Msz 8
#define KS 16
#define NMLPBLK 128              // 8 ntiles x 16 k-splits
#define TSPLIT 20
#define TCHUNK (Tsz / TSPLIT)    // 100

// ---------------- scratch -----------------------------------------------------
__device__ float g_part1[KS * Bsz * Asz];
__device__ float g_part2[KS * Bsz * Asz];
__device__ float g_cpart[TSPLIT * Bsz * Esz];
__device__ float g_esum[TSPLIT * Bsz];
__device__ float g_wmix[Bsz * Msz];
__device__ float g_loc[Bsz * Msz];
__device__ float g_scale[Bsz * Msz];
__device__ int   g_ctr[Bsz];     // ctx completion counters (self-resetting)
__device__ int   g_bar1;         // MLP grid barrier 1 (monotonic)
__device__ int   g_bar2;         // MLP grid barrier 2 (monotonic)
__device__ int   g_done;         // MLP exit counter; last block resets all

// ---------------- fused MLP: gemm1 -> barrier -> gemm2 -> barrier -> head ------
// grid 128 x 256. All blocks co-resident (148 SMs) => spin barriers are safe.
__global__ void __launch_bounds__(256)
mlp_fused_kernel(const float* __restrict__ ash,  const float* __restrict__ W1,
                 const float* __restrict__ b1,   const float* __restrict__ W2,
                 const float* __restrict__ Wlin, const float* __restrict__ blin,
                 const float* __restrict__ prev, float* __restrict__ out_loc) {
    __shared__ float As[64][33];
    __shared__ float Ws[64][33];
    __shared__ float sx[Asz];
    __shared__ float ys[24];

    const int tid = threadIdx.x;
    const int tx = tid & 15, ty = tid >> 4;
    const int lane = tid & 31, wrp = tid >> 5;
    const int ntile = blockIdx.x & 7;          // 8 n-tiles of 64
    const int ks = blockIdx.x >> 3;            // 16 k-splits
    const int nbase = ntile * 64;

    // ---- stage 1: part1[ks] = tanh(ash) @ W1^T  (K-slice 64 = two 32-chunks)
    {
        const int k0 = ks * (Rsz / KS);
        float acc[4][4] = {};
        for (int kk = 0; kk < Rsz / KS; kk += 32) {
            const int kc = k0 + kk + lane;
#pragma unroll
            for (int r = wrp; r < 64; r += 8) {
                As[r][lane] = tanhf(ash[r * Rsz + kc]);
                Ws[r][lane] = W1[(nbase + r) * Rsz + kc];
            }
            __syncthreads();
#pragma unroll
            for (int k = 0; k < 32; k++) {
                float a[4], w[4];
#pragma unroll
                for (int i = 0; i < 4; i++) a[i] = As[ty * 4 + i][k];
#pragma unroll
                for (int j = 0; j < 4; j++) w[j] = Ws[tx * 4 + j][k];
#pragma unroll
                for (int i = 0; i < 4; i++)
#pragma unroll
                    for (int j = 0; j < 4; j++) acc[i][j] = fmaf(a[i], w[j], acc[i][j]);
            }
            __syncthreads();
        }
#pragma unroll
        for (int i = 0; i < 4; i++)
#pragma unroll
            for (int j = 0; j < 4; j++)
                g_part1[(ks * 64 + ty * 4 + i) * Asz + nbase + tx * 4 + j] = acc[i][j];
    }

    // ---- grid barrier 1 (monotonic counter; reset at kernel end)
    __threadfence();
    __syncthreads();
    if (tid == 0) {
        atomicAdd(&g_bar1, 1);
        while (*(volatile int*)&g_bar1 < NMLPBLK) { }
    }
    __syncthreads();
    __threadfence();

    // ---- stage 2: part2[ks] = (sum part1 + b1) @ W2^T  (K-slice 32 = one chunk)
    {
        const int kc = ks * (Asz / KS) + lane;
        float acc[4][4] = {};
        const float bb = b1[kc];
#pragma unroll
        for (int r = wrp; r < 64; r += 8) {
            float s = bb;
#pragma unroll
            for (int p = 0; p < KS; p++) s += g_part1[(p * 64 + r) * Asz + kc];
            As[r][lane] = s;
            Ws[r][lane] = W2[(nbase + r) * Asz + kc];
        }
        __syncthreads();
#pragma unroll
        for (int k = 0; k < 32; k++) {
            float a[4], w[4];
#pragma unroll
            for (int i = 0; i < 4; i++) a[i] = As[ty * 4 + i][k];
#pragma unroll
            for (int j = 0; j < 4; j++) w[j] = Ws[tx * 4 + j][k];
#pragma unroll
            for (int i = 0; i < 4; i++)
#pragma unroll
                for (int j = 0; j < 4; j++) acc[i][j] = fmaf(a[i], w[j], acc[i][j]);
        }
        __syncthreads();
#pragma unroll
        for (int i = 0; i < 4; i++)
#pragma unroll
            for (int j = 0; j < 4; j++)
                g_part2[(ks * 64 + ty * 4 + i) * Asz + nbase + tx * 4 + j] = acc[i][j];
    }

    // ---- grid barrier 2
    __threadfence();
    __syncthreads();
    if (tid == 0) {
        atomicAdd(&g_bar2, 1);
        while (*(volatile int*)&g_bar2 < NMLPBLK) { }
    }
    __syncthreads();
    __threadfence();

    // ---- stage 3: head, one block per batch (blocks 0..63)
    if (blockIdx.x < Bsz) {
        const int b = blockIdx.x;
        for (int i = tid; i < Asz; i += 256) {
            float s = 0.0f;
#pragma unroll
            for (int p = 0; p < KS; p++) s += g_part2[(p * 64 + b) * Asz + i];
            sx[i] = tanhf(s);
        }
        __syncthreads();

        for (int o = wrp; o < 24; o += 8) {
            float s = 0.0f;
            const float* wr = Wlin + o * Asz;
            for (int k = lane; k < Asz; k += 32) s = fmaf(sx[k], wr[k], s);
#pragma unroll
            for (int off = 16; off > 0; off >>= 1)
                s += __shfl_down_sync(0xffffffffu, s, off);
            if (lane == 0) ys[o] = s + blin[o];
        }
        __syncthreads();

        if (tid < Msz) {
            const int m = tid;
            float wmix = 1.0f / (1.0f + expf(-ys[m]));
            float loc = prev[b * Msz + m] + 1.0f / (1.0f + expf(-ys[Msz + m]));
            float scl = 1.0f / (1.0f + expf(-ys[2 * Msz + m])) * 2.0f + 1.0f;
            g_wmix[b * Msz + m] = wmix;
            g_loc[b * Msz + m] = loc;
            g_scale[b * Msz + m] = scl;
            out_loc[b * Msz + m] = loc;
        }
    }

    // ---- exit: last block to finish resets the barrier counters for next replay
    __syncthreads();
    if (tid == 0) {
        __threadfence();
        int old = atomicAdd(&g_done, 1);
        if (old == NMLPBLK - 1) {
            g_bar1 = 0;
            g_bar2 = 0;
            g_done = 0;
            __threadfence();
        }
    }
}

// ---------------- fused alignment + exp + context + softmax-normalize ----------
// R4-proven config: grid (TSPLIT, Bsz), block 128, unroll-4 single accumulator.
// No max-subtraction: alignment in [0,8], exp safe, softmax identical.
__global__ void __launch_bounds__(128)
ctx_fused_kernel(const float* __restrict__ mem,
                 const unsigned char* __restrict__ mask,
                 float* __restrict__ out_w,
                 float* __restrict__ out_ctx) {
    const int s = blockIdx.x;
    const int b = blockIdx.y;
    const int tid = threadIdx.x;
    const int lane = tid & 31, wrp = tid >> 5;
    const int t0 = s * TCHUNK;

    __shared__ float ex[TCHUNK];
    __shared__ float sw[Msz], sl[Msz], ss[Msz];
    __shared__ float red[4];

    if (tid < Msz) {
        sw[tid] = g_wmix[b * Msz + tid];
        sl[tid] = g_loc[b * Msz + tid];
        ss[tid] = g_scale[b * Msz + tid];
    }
    __syncthreads();

    if (tid < TCHUNK) {
        const int t = t0 + tid;
        float al = 0.0f;
        const float ft = (float)t;
#pragma unroll
        for (int m = 0; m < Msz; m++) {
            float d = sl[m] - ft;
            float sc = ss[m];
            float z = 0.5f * (erff((d + 0.5f) * sc) - erff((d - 0.5f) * sc));
            al = fmaf(z, sw[m], al);
        }
        if (mask[b * Tsz + t]) al = 0.0f;
        float e = __expf(al);
        ex[tid] = e;
        out_w[b * Tsz + t] = e;             // rescaled by the last block
    }
    __syncthreads();

    {
        float v = (tid < TCHUNK) ? ex[tid] : 0.0f;
#pragma unroll
        for (int off = 16; off > 0; off >>= 1)
            v += __shfl_xor_sync(0xffffffffu, v, off);
        if (lane == 0) red[wrp] = v;
        __syncthreads();
        if (tid == 0) g_esum[s * Bsz + b] = red[0] + red[1] + red[2] + red[3];
    }

    const float4* mrow = (const float4*)(mem + (size_t)b * Tsz * Esz);
    float4 acc = make_float4(0.f, 0.f, 0.f, 0.f);
#pragma unroll 4
    for (int i = 0; i < TCHUNK; i++) {
        float w = ex[i];
        float4 v = __ldcs(mrow + (t0 + i) * (Esz / 4) + tid);
        acc.x = fmaf(w, v.x, acc.x);
        acc.y = fmaf(w, v.y, acc.y);
        acc.z = fmaf(w, v.z, acc.z);
        acc.w = fmaf(w, v.w, acc.w);
    }
    ((float4*)g_cpart)[(s * Bsz + b) * (Esz / 4) + tid] = acc;

    __threadfence();
    __syncthreads();
    __shared__ int done;
    if (tid == 0) done = atomicAdd(&g_ctr[b], 1);
    __syncthreads();

    if (done == TSPLIT - 1) {
        __threadfence();  // acquire
        float S = 0.0f;
#pragma unroll
        for (int p = 0; p < TSPLIT; p++) S += g_esum[p * Bsz + b];
        const float inv = 1.0f / S;

        float4 sum = make_float4(0.f, 0.f, 0.f, 0.f);
#pragma unroll
        for (int p = 0; p < TSPLIT; p++) {
            float4 v = ((const float4*)g_cpart)[(p * Bsz + b) * (Esz / 4) + tid];
            sum.x += v.x; sum.y += v.y; sum.z += v.z; sum.w += v.w;
        }
        sum.x *= inv; sum.y *= inv; sum.z *= inv; sum.w *= inv;
        ((float4*)out_ctx)[b * (Esz / 4) + tid] = sum;

        for (int t = tid; t < Tsz; t += 128)
            out_w[b * Tsz + t] *= inv;

        if (tid == 0) g_ctr[b] = 0;  // reset for next replay
    }
}

// ---------------- launch --------------------------------------------------------
extern "C" void kernel_launch(void* const* d_in, const int* in_sizes, int n_in,
                              void* d_out, int out_size) {
    const float* ash  = (const float*)d_in[0];
    const float* mem  = (const float*)d_in[1];
    const float* prev = (const float*)d_in[2];
    const unsigned char* mask = (const unsigned char*)d_in[3];
    const float* W1   = (const float*)d_in[4];
    const float* b1   = (const float*)d_in[5];
    const float* W2   = (const float*)d_in[6];
    const float* Wlin = (const float*)d_in[7];
    const float* blin = (const float*)d_in[8];

    float* out     = (float*)d_out;
    float* out_ctx = out;
    float* out_w   = out + Bsz * Esz;
    float* out_loc = out_w + Bsz * Tsz;

    mlp_fused_kernel<<<NMLPBLK, 256>>>(ash, W1, b1, W2, Wlin, blin, prev, out_loc);
    ctx_fused_kernel<<<dim3(TSPLIT, Bsz), 128>>>(mem, mask, out_w, out_ctx);
}